// round 14
// baseline (speedup 1.0000x reference)
#include <cuda_runtime.h>
#include <cuda_bf16.h>
#include <cuda_fp16.h>
#include <stdint.h>
#include <math.h>

#define BATCH 8
#define LSEQ  2048
#define DDIM  1024

typedef __nv_bfloat16 bf16;

// ---------------------------------------------------------------------------
// Scratch (device globals: no allocation allowed)
// ---------------------------------------------------------------------------
__device__ float  g_scores[(size_t)BATCH * LSEQ * LSEQ];           // 134 MB
__device__ float  g_maskv [(size_t)BATCH * LSEQ];                  // additive mask
__device__ bf16   g_xh [(size_t)BATCH * LSEQ * DDIM];
__device__ bf16   g_xl [(size_t)BATCH * LSEQ * DDIM];
__device__ __half g_xth[(size_t)BATCH * DDIM * LSEQ];              // x^T fp16 hi
__device__ bf16   g_wh [(size_t)DDIM * DDIM];
__device__ bf16   g_wl [(size_t)DDIM * DDIM];
__device__ bf16   g_ph [(size_t)BATCH * LSEQ * DDIM];
__device__ bf16   g_pl [(size_t)BATCH * LSEQ * DDIM];
__device__ __half g_ah [(size_t)BATCH * LSEQ * LSEQ];              // alpha fp16

// ---------------------------------------------------------------------------
// PTX helpers (base sm_103 target — NO tcgen05)
// ---------------------------------------------------------------------------
__device__ __forceinline__ uint32_t smem_u32(const void* p) {
    uint32_t a;
    asm("{ .reg .u64 t; cvta.to.shared.u64 t, %1; cvt.u32.u64 %0, t; }" : "=r"(a) : "l"(p));
    return a;
}

__device__ __forceinline__ void cpa16(uint32_t d, const void* s) {
    asm volatile("cp.async.cg.shared.global [%0], [%1], 16;" :: "r"(d), "l"(s) : "memory");
}

#define CP_COMMIT() asm volatile("cp.async.commit_group;" ::: "memory")
#define CP_WAIT1()  asm volatile("cp.async.wait_group 1;" ::: "memory")

#define LDSM4(r, addr) \
    asm volatile("ldmatrix.sync.aligned.m8n8.x4.shared.b16 {%0,%1,%2,%3}, [%4];" \
        : "=r"((r)[0]), "=r"((r)[1]), "=r"((r)[2]), "=r"((r)[3]) : "r"(addr))

#define MMA(d, a, b0, b1) \
    asm volatile("mma.sync.aligned.m16n8k16.row.col.f32.bf16.bf16.f32 " \
        "{%0,%1,%2,%3}, {%4,%5,%6,%7}, {%8,%9}, {%0,%1,%2,%3};" \
        : "+f"((d)[0]), "+f"((d)[1]), "+f"((d)[2]), "+f"((d)[3]) \
        : "r"((a)[0]), "r"((a)[1]), "r"((a)[2]), "r"((a)[3]), "r"(b0), "r"(b1))

#define MMAH(d, a, b0, b1) \
    asm volatile("mma.sync.aligned.m16n8k16.row.col.f32.f16.f16.f32 " \
        "{%0,%1,%2,%3}, {%4,%5,%6,%7}, {%8,%9}, {%0,%1,%2,%3};" \
        : "+f"((d)[0]), "+f"((d)[1]), "+f"((d)[2]), "+f"((d)[3]) \
        : "r"((a)[0]), "r"((a)[1]), "r"((a)[2]), "r"((a)[3]), "r"(b0), "r"(b1))

// ---------------------------------------------------------------------------
// 3-pass bf16 GEMM core, CTA 256x128, warp tile 64x32 (16 warps 4x4).
// Stage = K=32 (48KB): A 256 rows x 128B at +0 (row = [hi 32k | lo 32k],
// XOR swizzle), B 128 rows x 128B at +32768. 4 stages (192KB), 1 CTA/SM.
// B fragments double-buffered; A fragment reused hi->lo within each kk.
// ---------------------------------------------------------------------------
#define NTH 512
#define STG256 49152
#define SMEM_BYTES (4 * STG256)

__device__ __forceinline__ void issue_stage256(uint32_t sb, int s, int tid,
    const bf16* __restrict__ Ah, const bf16* __restrict__ Al, size_t lda,
    const bf16* __restrict__ Bh, const bf16* __restrict__ Bl, size_t ldb, int kc)
{
    const uint32_t base = sb + (uint32_t)(s & 3) * STG256;
    #pragma unroll
    for (int j = 0; j < 4; j++) {                    // A: 256 rows x 8 chunks
        const int q   = tid + j * NTH;               // 0..2047
        const int row = q >> 3;
        const int c   = q & 7;                       // 0-3 hi, 4-7 lo
        const uint32_t off = (uint32_t)(row * 128) + ((uint32_t)(c ^ (row & 7)) << 4);
        const bf16* sa = (c < 4) ? Ah + (size_t)row * lda + kc + c * 8
                                 : Al + (size_t)row * lda + kc + (c - 4) * 8;
        cpa16(base + off, sa);
    }
    #pragma unroll
    for (int j = 0; j < 2; j++) {                    // B: 128 rows x 8 chunks
        const int q   = tid + j * NTH;               // 0..1023
        const int row = q >> 3;
        const int c   = q & 7;
        const uint32_t off = 32768u + (uint32_t)(row * 128)
                           + ((uint32_t)(c ^ (row & 7)) << 4);
        const bf16* sbp = (c < 4) ? Bh + (size_t)row * ldb + kc + c * 8
                                  : Bl + (size_t)row * ldb + kc + (c - 4) * 8;
        cpa16(base + off, sbp);
    }
    CP_COMMIT();
}

// A: 4 m-tiles; hilo 0 = hi chunks (0..3), 1 = lo chunks (4..7); kk in {0,1}
__device__ __forceinline__ void load_a256(uint32_t stage, int kk, int hilo, int m0,
                                          int lane, uint32_t a[4][4])
{
    const int cb = kk * 2 + hilo * 4;
    const int rA = lane & 15, cA = lane >> 4;
    #pragma unroll
    for (int mt = 0; mt < 4; mt++) {
        const uint32_t rowb = stage + (uint32_t)((m0 + mt * 16 + rA) * 128);
        LDSM4(a[mt], rowb + ((uint32_t)((cb + cA) ^ (rA & 7)) << 4));
    }
}

__device__ __forceinline__ void load_b256(uint32_t stage, int kk, int n0, int lane,
                                          uint32_t bH[2][4], uint32_t bL[2][4])
{
    const int cb = kk * 2;
    const int rB = (lane & 7) + ((lane >> 4) << 3), cB = (lane >> 3) & 1;
    #pragma unroll
    for (int nt2 = 0; nt2 < 2; nt2++) {
        const uint32_t rowb = stage + 32768 + (uint32_t)((n0 + nt2 * 16 + rB) * 128);
        LDSM4(bH[nt2], rowb + ((uint32_t)((cb + cB)     ^ (rB & 7)) << 4));
        LDSM4(bL[nt2], rowb + ((uint32_t)((cb + 4 + cB) ^ (rB & 7)) << 4));
    }
}

__device__ __forceinline__ void pass256(float acc[4][4][4], const uint32_t a[4][4],
                                        const uint32_t b[2][4])
{
    #pragma unroll
    for (int mt = 0; mt < 4; mt++)
        #pragma unroll
        for (int nt = 0; nt < 4; nt++) {
            const int g = nt >> 1, o = (nt & 1) * 2;
            MMA(acc[mt][nt], a[mt], b[g][o], b[g][o + 1]);
        }
}

// nk = K / 32
__device__ __forceinline__ void run_gemm256(uint32_t sb, int tid,
    const bf16* __restrict__ Ah, const bf16* __restrict__ Al, size_t lda,
    const bf16* __restrict__ Bh, const bf16* __restrict__ Bl, size_t ldb, int nk,
    float acc[4][4][4])
{
    #pragma unroll
    for (int mt = 0; mt < 4; mt++)
        #pragma unroll
        for (int nt = 0; nt < 4; nt++)
            #pragma unroll
            for (int i = 0; i < 4; i++) acc[mt][nt][i] = 0.f;

    issue_stage256(sb, 0, tid, Ah, Al, lda, Bh, Bl, ldb, 0);
    issue_stage256(sb, 1, tid, Ah, Al, lda, Bh, Bl, ldb, 32);

    const int wid = tid >> 5, lane = tid & 31;
    const int m0 = (wid & 3) * 64, n0 = (wid >> 2) * 32;

    CP_WAIT1();                 // stage 0 resident
    __syncthreads();

    uint32_t aF[4][4], b0H[2][4], b0L[2][4], b1H[2][4], b1L[2][4];
    load_b256(sb, 0, n0, lane, b0H, b0L);

    for (int kt = 0; kt < nk; kt++) {
        const uint32_t cur = sb + (uint32_t)(kt & 3) * STG256;
        if (kt + 2 < nk)
            issue_stage256(sb, kt + 2, tid, Ah, Al, lda, Bh, Bl, ldb, (kt + 2) * 32);
        else
            CP_COMMIT();

        // ---- kk = 0 ----
        load_a256(cur, 0, 0, m0, lane, aF);          // A hi
        load_b256(cur, 1, n0, lane, b1H, b1L);       // prefetch kk1 B
        pass256(acc, aF, b0H);                       // hi*hi
        pass256(acc, aF, b0L);                       // hi*lo
        load_a256(cur, 0, 1, m0, lane, aF);          // A lo (reuse regs)
        pass256(acc, aF, b0H);                       // lo*hi
        // ---- kk = 1 ----
        load_a256(cur, 1, 0, m0, lane, aF);
        pass256(acc, aF, b1H);
        pass256(acc, aF, b1L);
        load_a256(cur, 1, 1, m0, lane, aF);
        pass256(acc, aF, b1H);

        CP_WAIT1();             // stage kt+1 resident
        __syncthreads();

        const int pkt = (kt + 1 < nk) ? kt + 1 : kt;
        load_b256(sb + (uint32_t)(pkt & 3) * STG256, 0, n0, lane, b0H, b0L);
    }
}

// ---------------------------------------------------------------------------
// 1-pass fp16 GEMM core (av): C(128x128) = Ah @ Bh^T.  (unchanged, proven)
// 256 threads, warp 64x32, K=64 stages x3 (96KB) -> 2 CTAs/SM, frag dbl-buf.
// ---------------------------------------------------------------------------
#define NTH_AV 256
#define STG_AV 32768
#define SMEM_AV (3 * STG_AV)

struct FragAv {
    uint32_t aH[4][4], bH[2][4];
};

__device__ __forceinline__ void issue_stage_av(uint32_t sb, int s, int tid,
    const __half* __restrict__ Ah, size_t lda,
    const __half* __restrict__ Bh, size_t ldb, int kc)
{
    const uint32_t base = sb + (uint32_t)(s % 3) * STG_AV;
    #pragma unroll
    for (int j = 0; j < 4; j++) {
        const int q   = tid + j * NTH_AV;
        const int row = q >> 3;
        const int c   = q & 7;
        const uint32_t off = (uint32_t)(row * 128) + ((uint32_t)(c ^ (row & 7)) << 4);
        cpa16(base + off, Ah + (size_t)row * lda + kc + c * 8);
    }
    #pragma unroll
    for (int j = 0; j < 4; j++) {
        const int q   = tid + j * NTH_AV;
        const int row = q >> 3;
        const int c   = q & 7;
        const uint32_t off = 16384u + (uint32_t)(row * 128)
                           + ((uint32_t)(c ^ (row & 7)) << 4);
        cpa16(base + off, Bh + (size_t)row * ldb + kc + c * 8);
    }
    CP_COMMIT();
}

__device__ __forceinline__ void load_frags_av(uint32_t stage, int kk, int m0, int n0,
                                              int lane, FragAv& f)
{
    const int cb = kk * 2;
    const int rA = lane & 15, cA = lane >> 4;
    const int rB = (lane & 7) + ((lane >> 4) << 3), cB = (lane >> 3) & 1;
    #pragma unroll
    for (int mt = 0; mt < 4; mt++) {
        const uint32_t rowb = stage + (uint32_t)((m0 + mt * 16 + rA) * 128);
        LDSM4(f.aH[mt], rowb + ((uint32_t)((cb + cA) ^ (rA & 7)) << 4));
    }
    #pragma unroll
    for (int nt2 = 0; nt2 < 2; nt2++) {
        const uint32_t rowb = stage + 16384 + (uint32_t)((n0 + nt2 * 16 + rB) * 128);
        LDSM4(f.bH[nt2], rowb + ((uint32_t)((cb + cB) ^ (rB & 7)) << 4));
    }
}

__device__ __forceinline__ void do_mmas_av(const FragAv& f, float acc[4][4][4]) {
    #pragma unroll
    for (int mt = 0; mt < 4; mt++)
        #pragma unroll
        for (int nt = 0; nt < 4; nt++) {
            const int g = nt >> 1, o = (nt & 1) * 2;
            MMAH(acc[mt][nt], f.aH[mt], f.bH[g][o], f.bH[g][o + 1]);
        }
}

__device__ __forceinline__ void run_gemm_av(uint32_t sb, int tid,
    const __half* __restrict__ Ah, size_t lda,
    const __half* __restrict__ Bh, size_t ldb, int nk,
    float acc[4][4][4])
{
    #pragma unroll
    for (int mt = 0; mt < 4; mt++)
        #pragma unroll
        for (int nt = 0; nt < 4; nt++)
            #pragma unroll
            for (int i = 0; i < 4; i++) acc[mt][nt][i] = 0.f;

    issue_stage_av(sb, 0, tid, Ah, lda, Bh, ldb, 0);
    issue_stage_av(sb, 1, tid, Ah, lda, Bh, ldb, 64);

    const int wid = tid >> 5, lane = tid & 31;
    const int m0 = (wid & 1) * 64, n0 = (wid >> 1) * 32;

    CP_WAIT1();
    __syncthreads();

    FragAv fa, fb;
    load_frags_av(sb, 0, m0, n0, lane, fa);

    for (int kt = 0; kt < nk; kt++) {
        const uint32_t cur = sb + (uint32_t)(kt % 3) * STG_AV;
        if (kt + 2 < nk)
            issue_stage_av(sb, kt + 2, tid, Ah, lda, Bh, ldb, (kt + 2) * 64);
        else
            CP_COMMIT();

        load_frags_av(cur, 1, m0, n0, lane, fb);
        do_mmas_av(fa, acc);
        load_frags_av(cur, 2, m0, n0, lane, fa);
        do_mmas_av(fb, acc);
        load_frags_av(cur, 3, m0, n0, lane, fb);
        do_mmas_av(fa, acc);

        CP_WAIT1();
        __syncthreads();

        const int pkt = (kt + 1 < nk) ? kt + 1 : kt;
        load_frags_av(sb + (uint32_t)(pkt % 3) * STG_AV, 0, m0, n0, lane, fa);
        do_mmas_av(fb, acc);
    }
}

__device__ __forceinline__ uint32_t packbf(float a, float b) {
    __nv_bfloat162 t = __floats2bfloat162_rn(a, b);
    return *reinterpret_cast<uint32_t*>(&t);
}
__device__ __forceinline__ uint32_t packh(float a, float b) {
    __half2 t = __floats2half2_rn(a, b);
    return *reinterpret_cast<uint32_t*>(&t);
}

// ---------------------------------------------------------------------------
// GEMM 1: proj = relu(x @ W^T + b) -> split bf16  (CTA 256x128)
// ---------------------------------------------------------------------------
__global__ __launch_bounds__(NTH, 1) void proj_gemm(const float* __restrict__ bias) {
    extern __shared__ char smem[];
    const uint32_t sb = smem_u32(smem);
    const int tid = threadIdx.x;
    const int mblk = blockIdx.y * 256, nblk = blockIdx.x * 128;

    float acc[4][4][4];
    run_gemm256(sb, tid,
                g_xh + (size_t)mblk * DDIM, g_xl + (size_t)mblk * DDIM, DDIM,
                g_wh + (size_t)nblk * DDIM, g_wl + (size_t)nblk * DDIM, DDIM,
                DDIM / 32, acc);

    const int wid = tid >> 5, lane = tid & 31;
    const int m0 = (wid & 3) * 64, n0 = (wid >> 2) * 32;
    const int quad = lane >> 2, tq = lane & 3;

    #pragma unroll
    for (int mt = 0; mt < 4; mt++)
        #pragma unroll
        for (int nt = 0; nt < 4; nt++) {
            const int col = nblk + n0 + nt * 8 + tq * 2;
            const float b0 = bias[col], b1 = bias[col + 1];
            #pragma unroll
            for (int h = 0; h < 2; h++) {
                const int row = mblk + m0 + mt * 16 + quad + h * 8;
                float v0 = fmaxf(acc[mt][nt][h * 2 + 0] + b0, 0.f);
                float v1 = fmaxf(acc[mt][nt][h * 2 + 1] + b1, 0.f);
                bf16 h0 = __float2bfloat16(v0), h1 = __float2bfloat16(v1);
                float l0 = v0 - __bfloat162float(h0), l1 = v1 - __bfloat162float(h1);
                *reinterpret_cast<uint32_t*>(g_ph + (size_t)row * DDIM + col) =
                    packbf(__bfloat162float(h0), __bfloat162float(h1));
                *reinterpret_cast<uint32_t*>(g_pl + (size_t)row * DDIM + col) =
                    packbf(l0, l1);
            }
        }
}

// ---------------------------------------------------------------------------
// GEMM 2 (symmetric, CTA 256x128): tiles (mi,nj) with nj >= 2*mi; raw scores.
// Direct write always; mirror write (transpose) only when nj >= 2*mi+2
// (exact complement cover, no double writes). Mask/diag applied in softmax.
// ---------------------------------------------------------------------------
__global__ __launch_bounds__(NTH, 1) void scores_gemm() {
    extern __shared__ char smem[];
    const uint32_t sb = smem_u32(smem);
    const int tid = threadIdx.x;
    const int b = blockIdx.y;
    int p = blockIdx.x;
    int mi = 0;
    while (p >= 16 - 2 * mi) { p -= 16 - 2 * mi; mi++; }
    const int nj = 2 * mi + p;
    const size_t pb = (size_t)b * LSEQ * DDIM;

    float acc[4][4][4];
    run_gemm256(sb, tid,
                g_ph + pb + (size_t)mi * 256 * DDIM, g_pl + pb + (size_t)mi * 256 * DDIM, DDIM,
                g_ph + pb + (size_t)nj * 128 * DDIM, g_pl + pb + (size_t)nj * 128 * DDIM, DDIM,
                DDIM / 32, acc);

    __syncthreads();
    float (*sS)[129] = reinterpret_cast<float(*)[129]>(smem);   // 256x129 f32 = 132KB

    const int wid = tid >> 5, lane = tid & 31;
    const int m0 = (wid & 3) * 64, n0 = (wid >> 2) * 32;
    const int quad = lane >> 2, tq = lane & 3;

    #pragma unroll
    for (int mt = 0; mt < 4; mt++)
        #pragma unroll
        for (int nt = 0; nt < 4; nt++) {
            const int c = n0 + nt * 8 + tq * 2;
            #pragma unroll
            for (int h = 0; h < 2; h++) {
                const int r = m0 + mt * 16 + quad + h * 8;
                sS[r][c]     = acc[mt][nt][h * 2 + 0];
                sS[r][c + 1] = acc[mt][nt][h * 2 + 1];
            }
        }
    __syncthreads();

    float* S = g_scores + (size_t)b * LSEQ * LSEQ;

    // direct: rows mi*256 + r, cols nj*128 + c
    {
        const int r  = tid & 255;
        const int c0 = (tid >> 8) * 64;
        float* Srow = S + (size_t)(mi * 256 + r) * LSEQ + nj * 128 + c0;
        #pragma unroll
        for (int cc = 0; cc < 64; cc += 4) {
            float4 v;
            v.x = sS[r][c0 + cc];
            v.y = sS[r][c0 + cc + 1];
            v.z = sS[r][c0 + cc + 2];
            v.w = sS[r][c0 + cc + 3];
            *reinterpret_cast<float4*>(Srow + cc) = v;
        }
    }
    // mirror: rows nj*128 + rr, cols mi*256 + c (transposed reads, pad 129 -> CF)
    if (nj >= 2 * mi + 2) {
        const int rr = tid & 127;
        const int c0 = (tid >> 7) * 64;
        float* Mrow = S + (size_t)(nj * 128 + rr) * LSEQ + mi * 256 + c0;
        #pragma unroll
        for (int cc = 0; cc < 64; cc += 4) {
            float4 v;
            v.x = sS[c0 + cc][rr];
            v.y = sS[c0 + cc + 1][rr];
            v.z = sS[c0 + cc + 2][rr];
            v.w = sS[c0 + cc + 3][rr];
            *reinterpret_cast<float4*>(Mrow + cc) = v;
        }
    }
}

// ---------------------------------------------------------------------------
// GEMM 3: out = alpha @ x   (fp16 1-pass, CTA 128x128, warp 64x32, 2 CTA/SM)
// ---------------------------------------------------------------------------
__global__ __launch_bounds__(NTH_AV, 2) void av_gemm(float* __restrict__ out) {
    extern __shared__ char smem[];
    const uint32_t sb = smem_u32(smem);
    const int tid = threadIdx.x;
    const int b = blockIdx.z;
    const int mblk = blockIdx.y * 128, nblk = blockIdx.x * 128;

    float acc[4][4][4];
    run_gemm_av(sb, tid,
                g_ah + ((size_t)b * LSEQ + mblk) * LSEQ, LSEQ,
                g_xth + ((size_t)b * DDIM + nblk) * LSEQ, LSEQ,
                LSEQ / 64, acc);

    const int wid = tid >> 5, lane = tid & 31;
    const int m0 = (wid & 1) * 64, n0 = (wid >> 1) * 32;
    const int quad = lane >> 2, tq = lane & 3;

    #pragma unroll
    for (int mt = 0; mt < 4; mt++)
        #pragma unroll
        for (int nt = 0; nt < 4; nt++) {
            const int col = nblk + n0 + nt * 8 + tq * 2;
            #pragma unroll
            for (int h = 0; h < 2; h++) {
                const int row = mblk + m0 + mt * 16 + quad + h * 8;
                float2 o;
                o.x = acc[mt][nt][h * 2 + 0];
                o.y = acc[mt][nt][h * 2 + 1];
                *reinterpret_cast<float2*>(out + ((size_t)b * LSEQ + row) * DDIM + col) = o;
            }
        }
}

// ---------------------------------------------------------------------------
// Softmax over keys. Applies additive mask (g_maskv) and diagonal rule:
// v[gi] = maskv[gi] (0 if unmasked -> diag zero; -inf if masked).
// ---------------------------------------------------------------------------
__global__ __launch_bounds__(256) void softmax_kernel() {
    const size_t row = blockIdx.x;
    const int b  = (int)(row >> 11);            // row / LSEQ
    const int gi = (int)(row & (LSEQ - 1));
    const float* p  = g_scores + row * LSEQ;
    const float* mv = g_maskv + (size_t)b * LSEQ;
    const int t = threadIdx.x;

    float4 v0 = reinterpret_cast<const float4*>(p)[t * 2];
    float4 v1 = reinterpret_cast<const float4*>(p)[t * 2 + 1];
    float4 m0 = reinterpret_cast<const float4*>(mv)[t * 2];
    float4 m1 = reinterpret_cast<const float4*>(mv)[t * 2 + 1];

    float v[8];
    v[0] = v0.x + m0.x; v[1] = v0.y + m0.y; v[2] = v0.z + m0.z; v[3] = v0.w + m0.w;
    v[4] = v1.x + m1.x; v[5] = v1.y + m1.y; v[6] = v1.z + m1.z; v[7] = v1.w + m1.w;
    const int base = t * 8;
    if (gi >= base && gi < base + 8) {
        const float md[8] = {m0.x, m0.y, m0.z, m0.w, m1.x, m1.y, m1.z, m1.w};
        v[gi - base] = md[gi - base];
    }

    float m = v[0];
    #pragma unroll
    for (int i = 1; i < 8; i++) m = fmaxf(m, v[i]);

    __shared__ float red[8];
    #pragma unroll
    for (int off = 16; off > 0; off >>= 1)
        m = fmaxf(m, __shfl_xor_sync(0xffffffffu, m, off));
    if ((t & 31) == 0) red[t >> 5] = m;
    __syncthreads();
    if (t == 0) {
        float mm = red[0];
        #pragma unroll
        for (int w = 1; w < 8; w++) mm = fmaxf(mm, red[w]);
        red[0] = mm;
    }
    __syncthreads();
    m = red[0];
    __syncthreads();

    float e[8];
    #pragma unroll
    for (int i = 0; i < 8; i++) e[i] = __expf(v[i] - m);
    float s = e[0] + e[1] + e[2] + e[3] + e[4] + e[5] + e[6] + e[7];
    #pragma unroll
    for (int off = 16; off > 0; off >>= 1)
        s += __shfl_xor_sync(0xffffffffu, s, off);
    if ((t & 31) == 0) red[t >> 5] = s;
    __syncthreads();
    if (t == 0) {
        float ss = 0.f;
        #pragma unroll
        for (int w = 0; w < 8; w++) ss += red[w];
        red[0] = ss;
    }
    __syncthreads();
    const float inv = 1.0f / red[0];

    uint32_t hh[4];
    #pragma unroll
    for (int i = 0; i < 4; i++)
        hh[i] = packh(e[2 * i] * inv, e[2 * i + 1] * inv);
    *reinterpret_cast<uint4*>(g_ah + row * LSEQ + t * 8) = *reinterpret_cast<uint4*>(hh);
}

// ---------------------------------------------------------------------------
// Fused x prep: read x once -> xh/xl (row-major bf16) + xth (fp16 transposed)
// ---------------------------------------------------------------------------
__global__ __launch_bounds__(256) void prep_x_kernel(const float* __restrict__ x) {
    __shared__ float t[32][33];
    const int b = blockIdx.z, d0 = blockIdx.x * 32, l0 = blockIdx.y * 32;
    const int tx = threadIdx.x & 31, ty = threadIdx.x >> 5;   // 32 x 8
    const float* xb = x + (size_t)b * LSEQ * DDIM;
    bf16* xh = g_xh + (size_t)b * LSEQ * DDIM;
    bf16* xl = g_xl + (size_t)b * LSEQ * DDIM;

    #pragma unroll
    for (int j = 0; j < 4; j++) {
        const int l = l0 + ty + j * 8;
        const float v = xb[(size_t)l * DDIM + d0 + tx];
        t[ty + j * 8][tx] = v;
        bf16 h = __float2bfloat16(v);
        xh[(size_t)l * DDIM + d0 + tx] = h;
        xl[(size_t)l * DDIM + d0 + tx] = __float2bfloat16(v - __bfloat162float(h));
    }
    __syncthreads();
    __half* oh = g_xth + (size_t)b * DDIM * LSEQ;
    #pragma unroll
    for (int j = 0; j < 4; j++) {
        float v = t[tx][ty + j * 8];
        oh[(size_t)(d0 + ty + j * 8) * LSEQ + l0 + tx] = __float2half_rn(v);
    }
}

// fp32 -> split-bf16 conversion (W)
__global__ __launch_bounds__(256) void split_kernel(const float* __restrict__ s,
                                                    bf16* __restrict__ hi,
                                                    bf16* __restrict__ lo, int n4) {
    const int i = blockIdx.x * 256 + threadIdx.x;
    if (i >= n4) return;
    float4 v = reinterpret_cast<const float4*>(s)[i];
    bf16 h0 = __float2bfloat16(v.x), h1 = __float2bfloat16(v.y);
    bf16 h2 = __float2bfloat16(v.z), h3 = __float2bfloat16(v.w);
    uint2 uh, ul;
    uh.x = packbf(__bfloat162float(h0), __bfloat162float(h1));
    uh.y = packbf(__bfloat162float(h2), __bfloat162float(h3));
    ul.x = packbf(v.x - __bfloat162float(h0), v.y - __bfloat162float(h1));
    ul.y = packbf(v.z - __bfloat162float(h2), v.w - __bfloat162float(h3));
    reinterpret_cast<uint2*>(hi)[i] = uh;
    reinterpret_cast<uint2*>(lo)[i] = ul;
}

// mask -> additive float vector (0 / -inf)
__global__ __launch_bounds__(256) void mask_kernel(const int* __restrict__ x_mask) {
    const int i = blockIdx.x * 256 + threadIdx.x;
    if (i < BATCH * LSEQ)
        g_maskv[i] = x_mask[i] ? -INFINITY : 0.f;
}

// ---------------------------------------------------------------------------
extern "C" void kernel_launch(void* const* d_in, const int* in_sizes, int n_in,
                              void* d_out, int out_size) {
    const float* x      = (const float*)d_in[0];   // [8, 2048, 1024]
    const int*   x_mask = (const int*)d_in[1];     // [8, 2048]
    const float* W      = (const float*)d_in[2];   // [1024, 1024]
    const float* bias   = (const float*)d_in[3];   // [1024]
    float* out = (float*)d_out;                    // [8, 2048, 1024]

    cudaFuncSetAttribute(proj_gemm,   cudaFuncAttributeMaxDynamicSharedMemorySize, SMEM_BYTES);
    cudaFuncSetAttribute(scores_gemm, cudaFuncAttributeMaxDynamicSharedMemorySize, SMEM_BYTES);
    cudaFuncSetAttribute(av_gemm,     cudaFuncAttributeMaxDynamicSharedMemorySize, SMEM_AV);

    bf16 *wh, *wl;
    cudaGetSymbolAddress((void**)&wh, g_wh);
    cudaGetSymbolAddress((void**)&wl, g_wl);

    const int nw4 = DDIM * DDIM / 4;

    split_kernel<<<(nw4 + 255) / 256, 256>>>(W, wh, wl, nw4);
    mask_kernel<<<(BATCH * LSEQ + 255) / 256, 256>>>(x_mask);
    prep_x_kernel<<<dim3(DDIM / 32, LSEQ / 32, BATCH), 256>>>(x);

    proj_gemm  <<<dim3(DDIM / 128, (BATCH * LSEQ) / 256), NTH, SMEM_BYTES>>>(bias);
    scores_gemm<<<dim3(72, BATCH), NTH, SMEM_BYTES>>>();
    softmax_kernel<<<BATCH * LSEQ, 256>>>();
    av_gemm    <<<dim3(DDIM / 128, LSEQ / 128, BATCH), NTH_AV, SMEM_AV>>>(out);
}

// round 15
// speedup vs baseline: 1.0097x; 1.0097x over previous
#include <cuda_runtime.h>
#include <cuda_bf16.h>
#include <cuda_fp16.h>
#include <stdint.h>
#include <math.h>

#define BATCH 8
#define LSEQ  2048
#define DDIM  1024

typedef __nv_bfloat16 bf16;

// ---------------------------------------------------------------------------
// Scratch (device globals: no allocation allowed)
// ---------------------------------------------------------------------------
__device__ float  g_scores[(size_t)BATCH * LSEQ * LSEQ];           // 134 MB
__device__ float  g_maskv [(size_t)BATCH * LSEQ];                  // additive mask
__device__ bf16   g_xh [(size_t)BATCH * LSEQ * DDIM];
__device__ bf16   g_xl [(size_t)BATCH * LSEQ * DDIM];
__device__ __half g_xth[(size_t)BATCH * DDIM * LSEQ];              // x^T fp16 hi
__device__ bf16   g_wh [(size_t)DDIM * DDIM];
__device__ bf16   g_wl [(size_t)DDIM * DDIM];
__device__ bf16   g_ph [(size_t)BATCH * LSEQ * DDIM];
__device__ bf16   g_pl [(size_t)BATCH * LSEQ * DDIM];
__device__ __half g_ah [(size_t)BATCH * LSEQ * LSEQ];              // alpha fp16

// ---------------------------------------------------------------------------
// PTX helpers (base sm_103 target — NO tcgen05)
// ---------------------------------------------------------------------------
__device__ __forceinline__ uint32_t smem_u32(const void* p) {
    uint32_t a;
    asm("{ .reg .u64 t; cvta.to.shared.u64 t, %1; cvt.u32.u64 %0, t; }" : "=r"(a) : "l"(p));
    return a;
}

__device__ __forceinline__ void cpa16(uint32_t d, const void* s) {
    asm volatile("cp.async.cg.shared.global [%0], [%1], 16;" :: "r"(d), "l"(s) : "memory");
}

#define CP_COMMIT() asm volatile("cp.async.commit_group;" ::: "memory")
#define CP_WAIT1()  asm volatile("cp.async.wait_group 1;" ::: "memory")

#define LDSM4(r, addr) \
    asm volatile("ldmatrix.sync.aligned.m8n8.x4.shared.b16 {%0,%1,%2,%3}, [%4];" \
        : "=r"((r)[0]), "=r"((r)[1]), "=r"((r)[2]), "=r"((r)[3]) : "r"(addr))

#define MMA(d, a, b0, b1) \
    asm volatile("mma.sync.aligned.m16n8k16.row.col.f32.bf16.bf16.f32 " \
        "{%0,%1,%2,%3}, {%4,%5,%6,%7}, {%8,%9}, {%0,%1,%2,%3};" \
        : "+f"((d)[0]), "+f"((d)[1]), "+f"((d)[2]), "+f"((d)[3]) \
        : "r"((a)[0]), "r"((a)[1]), "r"((a)[2]), "r"((a)[3]), "r"(b0), "r"(b1))

#define MMAH(d, a, b0, b1) \
    asm volatile("mma.sync.aligned.m16n8k16.row.col.f32.f16.f16.f32 " \
        "{%0,%1,%2,%3}, {%4,%5,%6,%7}, {%8,%9}, {%0,%1,%2,%3};" \
        : "+f"((d)[0]), "+f"((d)[1]), "+f"((d)[2]), "+f"((d)[3]) \
        : "r"((a)[0]), "r"((a)[1]), "r"((a)[2]), "r"((a)[3]), "r"(b0), "r"(b1))

// ===========================================================================
// Core 1 (proj): R13-proven 3-pass bf16, CTA 128x128, warp 32x32, 512 thr.
// Stage = K=64 (64KB), 3 stages (192KB). Frags double-buffered.
// ===========================================================================
#define NTH 512
#define STG    65536
#define SMEM_BYTES (3 * STG)

struct Frag {
    uint32_t aH[2][4], aL[2][4], bH[2][4], bL[2][4];
};

__device__ __forceinline__ void issue_stage(uint32_t sb, int s, int tid,
    const bf16* __restrict__ Ah, const bf16* __restrict__ Al, size_t lda,
    const bf16* __restrict__ Bh, const bf16* __restrict__ Bl, size_t ldb, int kc)
{
    const uint32_t base = sb + (uint32_t)(s % 3) * STG;
    #pragma unroll
    for (int panel = 0; panel < 2; panel++) {
        const int kcp = kc + panel * 32;
        const uint32_t pb = base + (uint32_t)panel * 16384;
        #pragma unroll
        for (int j = 0; j < 2; j++) {
            const int q   = tid + j * NTH;       // 0..1023
            const int row = q >> 3;
            const int c   = q & 7;               // 0-3 hi, 4-7 lo
            const uint32_t off = (uint32_t)(row * 128) + ((uint32_t)(c ^ (row & 7)) << 4);
            const bf16* sa = (c < 4) ? Ah + (size_t)row * lda + kcp + c * 8
                                     : Al + (size_t)row * lda + kcp + (c - 4) * 8;
            const bf16* sbp = (c < 4) ? Bh + (size_t)row * ldb + kcp + c * 8
                                      : Bl + (size_t)row * ldb + kcp + (c - 4) * 8;
            cpa16(pb + off, sa);
            cpa16(pb + 32768 + off, sbp);
        }
    }
    CP_COMMIT();
}

__device__ __forceinline__ void load_frags(uint32_t stage, int kk, int m0, int n0,
                                           int lane, Frag& f)
{
    const uint32_t base = stage + (uint32_t)(kk >> 1) * 16384;
    const int cb = (kk & 1) * 2;
    const int rA = lane & 15, cA = lane >> 4;
    const int rB = (lane & 7) + ((lane >> 4) << 3), cB = (lane >> 3) & 1;
    #pragma unroll
    for (int mt = 0; mt < 2; mt++) {
        const uint32_t rowb = base + (uint32_t)((m0 + mt * 16 + rA) * 128);
        LDSM4(f.aH[mt], rowb + ((uint32_t)((cb + cA)     ^ (rA & 7)) << 4));
        LDSM4(f.aL[mt], rowb + ((uint32_t)((cb + 4 + cA) ^ (rA & 7)) << 4));
    }
    #pragma unroll
    for (int nt2 = 0; nt2 < 2; nt2++) {
        const uint32_t rowb = base + 32768 + (uint32_t)((n0 + nt2 * 16 + rB) * 128);
        LDSM4(f.bH[nt2], rowb + ((uint32_t)((cb + cB)     ^ (rB & 7)) << 4));
        LDSM4(f.bL[nt2], rowb + ((uint32_t)((cb + 4 + cB) ^ (rB & 7)) << 4));
    }
}

__device__ __forceinline__ void do_mmas(const Frag& f, float acc[2][4][4]) {
    #pragma unroll
    for (int mt = 0; mt < 2; mt++)
        #pragma unroll
        for (int nt = 0; nt < 4; nt++) {
            const int g = nt >> 1, o = (nt & 1) * 2;
            MMA(acc[mt][nt], f.aH[mt], f.bH[g][o], f.bH[g][o + 1]);
        }
    #pragma unroll
    for (int mt = 0; mt < 2; mt++)
        #pragma unroll
        for (int nt = 0; nt < 4; nt++) {
            const int g = nt >> 1, o = (nt & 1) * 2;
            MMA(acc[mt][nt], f.aH[mt], f.bL[g][o], f.bL[g][o + 1]);
        }
    #pragma unroll
    for (int mt = 0; mt < 2; mt++)
        #pragma unroll
        for (int nt = 0; nt < 4; nt++) {
            const int g = nt >> 1, o = (nt & 1) * 2;
            MMA(acc[mt][nt], f.aL[mt], f.bH[g][o], f.bH[g][o + 1]);
        }
}

__device__ __forceinline__ void run_gemm(uint32_t sb, int tid,
    const bf16* __restrict__ Ah, const bf16* __restrict__ Al, size_t lda,
    const bf16* __restrict__ Bh, const bf16* __restrict__ Bl, size_t ldb, int nk,
    float acc[2][4][4])
{
    #pragma unroll
    for (int mt = 0; mt < 2; mt++)
        #pragma unroll
        for (int nt = 0; nt < 4; nt++)
            #pragma unroll
            for (int i = 0; i < 4; i++) acc[mt][nt][i] = 0.f;

    issue_stage(sb, 0, tid, Ah, Al, lda, Bh, Bl, ldb, 0);
    issue_stage(sb, 1, tid, Ah, Al, lda, Bh, Bl, ldb, 64);

    const int wid = tid >> 5, lane = tid & 31;
    const int m0 = (wid & 3) * 32, n0 = (wid >> 2) * 32;

    CP_WAIT1();
    __syncthreads();

    Frag fa, fb;
    load_frags(sb, 0, m0, n0, lane, fa);

    for (int kt = 0; kt < nk; kt++) {
        const uint32_t cur = sb + (uint32_t)(kt % 3) * STG;
        if (kt + 2 < nk)
            issue_stage(sb, kt + 2, tid, Ah, Al, lda, Bh, Bl, ldb, (kt + 2) * 64);
        else
            CP_COMMIT();

        load_frags(cur, 1, m0, n0, lane, fb);
        do_mmas(fa, acc);
        load_frags(cur, 2, m0, n0, lane, fa);
        do_mmas(fb, acc);
        load_frags(cur, 3, m0, n0, lane, fb);
        do_mmas(fa, acc);

        CP_WAIT1();
        __syncthreads();

        const int pkt = (kt + 1 < nk) ? kt + 1 : kt;
        load_frags(sb + (uint32_t)(pkt % 3) * STG, 0, m0, n0, lane, fa);
        do_mmas(fb, acc);
    }
}

// ===========================================================================
// Core 2 (scores): 3-pass bf16, CTA 256x128, warp 64x32, 512 thr.
// Stage = K=32 (48KB: A 256x128B, B 128x128B), 4 stages (192KB).
// Separate aH/aL register arrays: all 12 LDSM per kk issue as one burst
// before the 48 MMAs (fixes R14's serial A reload).
// ===========================================================================
#define STG256 49152
#define SMEM_SC (4 * STG256)

__device__ __forceinline__ void issue_stage256(uint32_t sb, int s, int tid,
    const bf16* __restrict__ Ah, const bf16* __restrict__ Al, size_t lda,
    const bf16* __restrict__ Bh, const bf16* __restrict__ Bl, size_t ldb, int kc)
{
    const uint32_t base = sb + (uint32_t)(s & 3) * STG256;
    #pragma unroll
    for (int j = 0; j < 4; j++) {                    // A: 256 rows x 8 chunks
        const int q   = tid + j * NTH;               // 0..2047
        const int row = q >> 3;
        const int c   = q & 7;                       // 0-3 hi, 4-7 lo
        const uint32_t off = (uint32_t)(row * 128) + ((uint32_t)(c ^ (row & 7)) << 4);
        const bf16* sa = (c < 4) ? Ah + (size_t)row * lda + kc + c * 8
                                 : Al + (size_t)row * lda + kc + (c - 4) * 8;
        cpa16(base + off, sa);
    }
    #pragma unroll
    for (int j = 0; j < 2; j++) {                    // B: 128 rows x 8 chunks
        const int q   = tid + j * NTH;               // 0..1023
        const int row = q >> 3;
        const int c   = q & 7;
        const uint32_t off = 32768u + (uint32_t)(row * 128)
                           + ((uint32_t)(c ^ (row & 7)) << 4);
        const bf16* sbp = (c < 4) ? Bh + (size_t)row * ldb + kc + c * 8
                                  : Bl + (size_t)row * ldb + kc + (c - 4) * 8;
        cpa16(base + off, sbp);
    }
    CP_COMMIT();
}

__device__ __forceinline__ void load_a256(uint32_t stage, int kk, int hilo, int m0,
                                          int lane, uint32_t a[4][4])
{
    const int cb = kk * 2 + hilo * 4;
    const int rA = lane & 15, cA = lane >> 4;
    #pragma unroll
    for (int mt = 0; mt < 4; mt++) {
        const uint32_t rowb = stage + (uint32_t)((m0 + mt * 16 + rA) * 128);
        LDSM4(a[mt], rowb + ((uint32_t)((cb + cA) ^ (rA & 7)) << 4));
    }
}

__device__ __forceinline__ void load_b256(uint32_t stage, int kk, int n0, int lane,
                                          uint32_t bH[2][4], uint32_t bL[2][4])
{
    const int cb = kk * 2;
    const int rB = (lane & 7) + ((lane >> 4) << 3), cB = (lane >> 3) & 1;
    #pragma unroll
    for (int nt2 = 0; nt2 < 2; nt2++) {
        const uint32_t rowb = stage + 32768 + (uint32_t)((n0 + nt2 * 16 + rB) * 128);
        LDSM4(bH[nt2], rowb + ((uint32_t)((cb + cB)     ^ (rB & 7)) << 4));
        LDSM4(bL[nt2], rowb + ((uint32_t)((cb + 4 + cB) ^ (rB & 7)) << 4));
    }
}

__device__ __forceinline__ void pass256(float acc[4][4][4], const uint32_t a[4][4],
                                        const uint32_t b[2][4])
{
    #pragma unroll
    for (int mt = 0; mt < 4; mt++)
        #pragma unroll
        for (int nt = 0; nt < 4; nt++) {
            const int g = nt >> 1, o = (nt & 1) * 2;
            MMA(acc[mt][nt], a[mt], b[g][o], b[g][o + 1]);
        }
}

// nk = K / 32
__device__ __forceinline__ void run_gemm256(uint32_t sb, int tid,
    const bf16* __restrict__ Ah, const bf16* __restrict__ Al, size_t lda,
    const bf16* __restrict__ Bh, const bf16* __restrict__ Bl, size_t ldb, int nk,
    float acc[4][4][4])
{
    #pragma unroll
    for (int mt = 0; mt < 4; mt++)
        #pragma unroll
        for (int nt = 0; nt < 4; nt++)
            #pragma unroll
            for (int i = 0; i < 4; i++) acc[mt][nt][i] = 0.f;

    issue_stage256(sb, 0, tid, Ah, Al, lda, Bh, Bl, ldb, 0);
    issue_stage256(sb, 1, tid, Ah, Al, lda, Bh, Bl, ldb, 32);

    const int wid = tid >> 5, lane = tid & 31;
    const int m0 = (wid & 3) * 64, n0 = (wid >> 2) * 32;

    CP_WAIT1();                 // stage 0 resident
    __syncthreads();

    uint32_t aH[4][4], aL[4][4], bH[2][4], bL[2][4];

    for (int kt = 0; kt < nk; kt++) {
        const uint32_t cur = sb + (uint32_t)(kt & 3) * STG256;
        if (kt + 2 < nk)
            issue_stage256(sb, kt + 2, tid, Ah, Al, lda, Bh, Bl, ldb, (kt + 2) * 32);
        else
            CP_COMMIT();

        #pragma unroll
        for (int kk = 0; kk < 2; kk++) {
            // burst: 12 LDSM into distinct registers, then 48 MMAs
            load_b256(cur, kk, n0, lane, bH, bL);
            load_a256(cur, kk, 0, m0, lane, aH);
            load_a256(cur, kk, 1, m0, lane, aL);
            pass256(acc, aH, bH);
            pass256(acc, aH, bL);
            pass256(acc, aL, bH);
        }

        CP_WAIT1();             // stage kt+1 resident
        __syncthreads();
    }
}

// ===========================================================================
// Core 3 (av): 1-pass fp16, CTA 128x128, warp 64x32, 256 thr, 2 CTA/SM.
// ===========================================================================
#define NTH_AV 256
#define STG_AV 32768
#define SMEM_AV (3 * STG_AV)

struct FragAv {
    uint32_t aH[4][4], bH[2][4];
};

__device__ __forceinline__ void issue_stage_av(uint32_t sb, int s, int tid,
    const __half* __restrict__ Ah, size_t lda,
    const __half* __restrict__ Bh, size_t ldb, int kc)
{
    const uint32_t base = sb + (uint32_t)(s % 3) * STG_AV;
    #pragma unroll
    for (int j = 0; j < 4; j++) {
        const int q   = tid + j * NTH_AV;
        const int row = q >> 3;
        const int c   = q & 7;
        const uint32_t off = (uint32_t)(row * 128) + ((uint32_t)(c ^ (row & 7)) << 4);
        cpa16(base + off, Ah + (size_t)row * lda + kc + c * 8);
    }
    #pragma unroll
    for (int j = 0; j < 4; j++) {
        const int q   = tid + j * NTH_AV;
        const int row = q >> 3;
        const int c   = q & 7;
        const uint32_t off = 16384u + (uint32_t)(row * 128)
                           + ((uint32_t)(c ^ (row & 7)) << 4);
        cpa16(base + off, Bh + (size_t)row * ldb + kc + c * 8);
    }
    CP_COMMIT();
}

__device__ __forceinline__ void load_frags_av(uint32_t stage, int kk, int m0, int n0,
                                              int lane, FragAv& f)
{
    const int cb = kk * 2;
    const int rA = lane & 15, cA = lane >> 4;
    const int rB = (lane & 7) + ((lane >> 4) << 3), cB = (lane >> 3) & 1;
    #pragma unroll
    for (int mt = 0; mt < 4; mt++) {
        const uint32_t rowb = stage + (uint32_t)((m0 + mt * 16 + rA) * 128);
        LDSM4(f.aH[mt], rowb + ((uint32_t)((cb + cA) ^ (rA & 7)) << 4));
    }
    #pragma unroll
    for (int nt2 = 0; nt2 < 2; nt2++) {
        const uint32_t rowb = stage + 16384 + (uint32_t)((n0 + nt2 * 16 + rB) * 128);
        LDSM4(f.bH[nt2], rowb + ((uint32_t)((cb + cB) ^ (rB & 7)) << 4));
    }
}

__device__ __forceinline__ void do_mmas_av(const FragAv& f, float acc[4][4][4]) {
    #pragma unroll
    for (int mt = 0; mt < 4; mt++)
        #pragma unroll
        for (int nt = 0; nt < 4; nt++) {
            const int g = nt >> 1, o = (nt & 1) * 2;
            MMAH(acc[mt][nt], f.aH[mt], f.bH[g][o], f.bH[g][o + 1]);
        }
}

__device__ __forceinline__ void run_gemm_av(uint32_t sb, int tid,
    const __half* __restrict__ Ah, size_t lda,
    const __half* __restrict__ Bh, size_t ldb, int nk,
    float acc[4][4][4])
{
    #pragma unroll
    for (int mt = 0; mt < 4; mt++)
        #pragma unroll
        for (int nt = 0; nt < 4; nt++)
            #pragma unroll
            for (int i = 0; i < 4; i++) acc[mt][nt][i] = 0.f;

    issue_stage_av(sb, 0, tid, Ah, lda, Bh, ldb, 0);
    issue_stage_av(sb, 1, tid, Ah, lda, Bh, ldb, 64);

    const int wid = tid >> 5, lane = tid & 31;
    const int m0 = (wid & 1) * 64, n0 = (wid >> 1) * 32;

    CP_WAIT1();
    __syncthreads();

    FragAv fa, fb;
    load_frags_av(sb, 0, m0, n0, lane, fa);

    for (int kt = 0; kt < nk; kt++) {
        const uint32_t cur = sb + (uint32_t)(kt % 3) * STG_AV;
        if (kt + 2 < nk)
            issue_stage_av(sb, kt + 2, tid, Ah, lda, Bh, ldb, (kt + 2) * 64);
        else
            CP_COMMIT();

        load_frags_av(cur, 1, m0, n0, lane, fb);
        do_mmas_av(fa, acc);
        load_frags_av(cur, 2, m0, n0, lane, fa);
        do_mmas_av(fb, acc);
        load_frags_av(cur, 3, m0, n0, lane, fb);
        do_mmas_av(fa, acc);

        CP_WAIT1();
        __syncthreads();

        const int pkt = (kt + 1 < nk) ? kt + 1 : kt;
        load_frags_av(sb + (uint32_t)(pkt % 3) * STG_AV, 0, m0, n0, lane, fa);
        do_mmas_av(fb, acc);
    }
}

__device__ __forceinline__ uint32_t packbf(float a, float b) {
    __nv_bfloat162 t = __floats2bfloat162_rn(a, b);
    return *reinterpret_cast<uint32_t*>(&t);
}
__device__ __forceinline__ uint32_t packh(float a, float b) {
    __half2 t = __floats2half2_rn(a, b);
    return *reinterpret_cast<uint32_t*>(&t);
}

// ---------------------------------------------------------------------------
// GEMM 1: proj = relu(x @ W^T + b) -> split bf16  (R13 core, CTA 128x128)
// ---------------------------------------------------------------------------
__global__ __launch_bounds__(NTH, 1) void proj_gemm(const float* __restrict__ bias) {
    extern __shared__ char smem[];
    const uint32_t sb = smem_u32(smem);
    const int tid = threadIdx.x;
    const int mblk = blockIdx.y * 128, nblk = blockIdx.x * 128;

    float acc[2][4][4];
    run_gemm(sb, tid,
             g_xh + (size_t)mblk * DDIM, g_xl + (size_t)mblk * DDIM, DDIM,
             g_wh + (size_t)nblk * DDIM, g_wl + (size_t)nblk * DDIM, DDIM,
             DDIM / 64, acc);

    const int wid = tid >> 5, lane = tid & 31;
    const int m0 = (wid & 3) * 32, n0 = (wid >> 2) * 32;
    const int quad = lane >> 2, tq = lane & 3;

    #pragma unroll
    for (int mt = 0; mt < 2; mt++)
        #pragma unroll
        for (int nt = 0; nt < 4; nt++) {
            const int col = nblk + n0 + nt * 8 + tq * 2;
            const float b0 = bias[col], b1 = bias[col + 1];
            #pragma unroll
            for (int h = 0; h < 2; h++) {
                const int row = mblk + m0 + mt * 16 + quad + h * 8;
                float v0 = fmaxf(acc[mt][nt][h * 2 + 0] + b0, 0.f);
                float v1 = fmaxf(acc[mt][nt][h * 2 + 1] + b1, 0.f);
                bf16 h0 = __float2bfloat16(v0), h1 = __float2bfloat16(v1);
                float l0 = v0 - __bfloat162float(h0), l1 = v1 - __bfloat162float(h1);
                *reinterpret_cast<uint32_t*>(g_ph + (size_t)row * DDIM + col) =
                    packbf(__bfloat162float(h0), __bfloat162float(h1));
                *reinterpret_cast<uint32_t*>(g_pl + (size_t)row * DDIM + col) =
                    packbf(l0, l1);
            }
        }
}

// ---------------------------------------------------------------------------
// GEMM 2 (symmetric, CTA 256x128): tiles (mi,nj) with nj >= 2*mi; raw scores.
// Direct write always; mirror write only when nj >= 2*mi+2 (exact cover).
// Mask/diag applied in softmax.
// ---------------------------------------------------------------------------
__global__ __launch_bounds__(NTH, 1) void scores_gemm() {
    extern __shared__ char smem[];
    const uint32_t sb = smem_u32(smem);
    const int tid = threadIdx.x;
    const int b = blockIdx.y;
    int p = blockIdx.x;
    int mi = 0;
    while (p >= 16 - 2 * mi) { p -= 16 - 2 * mi; mi++; }
    const int nj = 2 * mi + p;
    const size_t pb = (size_t)b * LSEQ * DDIM;

    float acc[4][4][4];
    run_gemm256(sb, tid,
                g_ph + pb + (size_t)mi * 256 * DDIM, g_pl + pb + (size_t)mi * 256 * DDIM, DDIM,
                g_ph + pb + (size_t)nj * 128 * DDIM, g_pl + pb + (size_t)nj * 128 * DDIM, DDIM,
                DDIM / 32, acc);

    __syncthreads();
    float (*sS)[129] = reinterpret_cast<float(*)[129]>(smem);   // 256x129 f32 = 132KB

    const int wid = tid >> 5, lane = tid & 31;
    const int m0 = (wid & 3) * 64, n0 = (wid >> 2) * 32;
    const int quad = lane >> 2, tq = lane & 3;

    #pragma unroll
    for (int mt = 0; mt < 4; mt++)
        #pragma unroll
        for (int nt = 0; nt < 4; nt++) {
            const int c = n0 + nt * 8 + tq * 2;
            #pragma unroll
            for (int h = 0; h < 2; h++) {
                const int r = m0 + mt * 16 + quad + h * 8;
                sS[r][c]     = acc[mt][nt][h * 2 + 0];
                sS[r][c + 1] = acc[mt][nt][h * 2 + 1];
            }
        }
    __syncthreads();

    float* S = g_scores + (size_t)b * LSEQ * LSEQ;

    // direct: rows mi*256 + r, cols nj*128 + c
    {
        const int r  = tid & 255;
        const int c0 = (tid >> 8) * 64;
        float* Srow = S + (size_t)(mi * 256 + r) * LSEQ + nj * 128 + c0;
        #pragma unroll
        for (int cc = 0; cc < 64; cc += 4) {
            float4 v;
            v.x = sS[r][c0 + cc];
            v.y = sS[r][c0 + cc + 1];
            v.z = sS[r][c0 + cc + 2];
            v.w = sS[r][c0 + cc + 3];
            *reinterpret_cast<float4*>(Srow + cc) = v;
        }
    }
    // mirror: rows nj*128 + rr, cols mi*256 + c
    if (nj >= 2 * mi + 2) {
        const int rr = tid & 127;
        const int c0 = (tid >> 7) * 64;
        float* Mrow = S + (size_t)(nj * 128 + rr) * LSEQ + mi * 256 + c0;
        #pragma unroll
        for (int cc = 0; cc < 64; cc += 4) {
            float4 v;
            v.x = sS[c0 + cc][rr];
            v.y = sS[c0 + cc + 1][rr];
            v.z = sS[c0 + cc + 2][rr];
            v.w = sS[c0 + cc + 3][rr];
            *reinterpret_cast<float4*>(Mrow + cc) = v;
        }
    }
}

// ---------------------------------------------------------------------------
// GEMM 3: out = alpha @ x   (fp16 1-pass, CTA 128x128, warp 64x32, 2 CTA/SM)
// ---------------------------------------------------------------------------
__global__ __launch_bounds__(NTH_AV, 2) void av_gemm(float* __restrict__ out) {
    extern __shared__ char smem[];
    const uint32_t sb = smem_u32(smem);
    const int tid = threadIdx.x;
    const int b = blockIdx.z;
    const int mblk = blockIdx.y * 128, nblk = blockIdx.x * 128;

    float acc[4][4][4];
    run_gemm_av(sb, tid,
                g_ah + ((size_t)b * LSEQ + mblk) * LSEQ, LSEQ,
                g_xth + ((size_t)b * DDIM + nblk) * LSEQ, LSEQ,
                LSEQ / 64, acc);

    const int wid = tid >> 5, lane = tid & 31;
    const int m0 = (wid & 1) * 64, n0 = (wid >> 1) * 32;
    const int quad = lane >> 2, tq = lane & 3;

    #pragma unroll
    for (int mt = 0; mt < 4; mt++)
        #pragma unroll
        for (int nt = 0; nt < 4; nt++) {
            const int col = nblk + n0 + nt * 8 + tq * 2;
            #pragma unroll
            for (int h = 0; h < 2; h++) {
                const int row = mblk + m0 + mt * 16 + quad + h * 8;
                float2 o;
                o.x = acc[mt][nt][h * 2 + 0];
                o.y = acc[mt][nt][h * 2 + 1];
                *reinterpret_cast<float2*>(out + ((size_t)b * LSEQ + row) * DDIM + col) = o;
            }
        }
}

// ---------------------------------------------------------------------------
// Softmax over keys (mask + diag applied here via g_maskv)
// ---------------------------------------------------------------------------
__global__ __launch_bounds__(256) void softmax_kernel() {
    const size_t row = blockIdx.x;
    const int b  = (int)(row >> 11);
    const int gi = (int)(row & (LSEQ - 1));
    const float* p  = g_scores + row * LSEQ;
    const float* mv = g_maskv + (size_t)b * LSEQ;
    const int t = threadIdx.x;

    float4 v0 = reinterpret_cast<const float4*>(p)[t * 2];
    float4 v1 = reinterpret_cast<const float4*>(p)[t * 2 + 1];
    float4 m0 = reinterpret_cast<const float4*>(mv)[t * 2];
    float4 m1 = reinterpret_cast<const float4*>(mv)[t * 2 + 1];

    float v[8];
    v[0] = v0.x + m0.x; v[1] = v0.y + m0.y; v[2] = v0.z + m0.z; v[3] = v0.w + m0.w;
    v[4] = v1.x + m1.x; v[5] = v1.y + m1.y; v[6] = v1.z + m1.z; v[7] = v1.w + m1.w;
    const int base = t * 8;
    if (gi >= base && gi < base + 8) {
        const float md[8] = {m0.x, m0.y, m0.z, m0.w, m1.x, m1.y, m1.z, m1.w};
        v[gi - base] = md[gi - base];
    }

    float m = v[0];
    #pragma unroll
    for (int i = 1; i < 8; i++) m = fmaxf(m, v[i]);

    __shared__ float red[8];
    #pragma unroll
    for (int off = 16; off > 0; off >>= 1)
        m = fmaxf(m, __shfl_xor_sync(0xffffffffu, m, off));
    if ((t & 31) == 0) red[t >> 5] = m;
    __syncthreads();
    if (t == 0) {
        float mm = red[0];
        #pragma unroll
        for (int w = 1; w < 8; w++) mm = fmaxf(mm, red[w]);
        red[0] = mm;
    }
    __syncthreads();
    m = red[0];
    __syncthreads();

    float e[8];
    #pragma unroll
    for (int i = 0; i < 8; i++) e[i] = __expf(v[i] - m);
    float s = e[0] + e[1] + e[2] + e[3] + e[4] + e[5] + e[6] + e[7];
    #pragma unroll
    for (int off = 16; off > 0; off >>= 1)
        s += __shfl_xor_sync(0xffffffffu, s, off);
    if ((t & 31) == 0) red[t >> 5] = s;
    __syncthreads();
    if (t == 0) {
        float ss = 0.f;
        #pragma unroll
        for (int w = 0; w < 8; w++) ss += red[w];
        red[0] = ss;
    }
    __syncthreads();
    const float inv = 1.0f / red[0];

    uint32_t hh[4];
    #pragma unroll
    for (int i = 0; i < 4; i++)
        hh[i] = packh(e[2 * i] * inv, e[2 * i + 1] * inv);
    *reinterpret_cast<uint4*>(g_ah + row * LSEQ + t * 8) = *reinterpret_cast<uint4*>(hh);
}

// ---------------------------------------------------------------------------
// Fused x prep: read x once -> xh/xl (row-major bf16) + xth (fp16 transposed)
// ---------------------------------------------------------------------------
__global__ __launch_bounds__(256) void prep_x_kernel(const float* __restrict__ x) {
    __shared__ float t[32][33];
    const int b = blockIdx.z, d0 = blockIdx.x * 32, l0 = blockIdx.y * 32;
    const int tx = threadIdx.x & 31, ty = threadIdx.x >> 5;
    const float* xb = x + (size_t)b * LSEQ * DDIM;
    bf16* xh = g_xh + (size_t)b * LSEQ * DDIM;
    bf16* xl = g_xl + (size_t)b * LSEQ * DDIM;

    #pragma unroll
    for (int j = 0; j < 4; j++) {
        const int l = l0 + ty + j * 8;
        const float v = xb[(size_t)l * DDIM + d0 + tx];
        t[ty + j * 8][tx] = v;
        bf16 h = __float2bfloat16(v);
        xh[(size_t)l * DDIM + d0 + tx] = h;
        xl[(size_t)l * DDIM + d0 + tx] = __float2bfloat16(v - __bfloat162float(h));
    }
    __syncthreads();
    __half* oh = g_xth + (size_t)b * DDIM * LSEQ;
    #pragma unroll
    for (int j = 0; j < 4; j++) {
        float v = t[tx][ty + j * 8];
        oh[(size_t)(d0 + ty + j * 8) * LSEQ + l0 + tx] = __float2half_rn(v);
    }
}

// fp32 -> split-bf16 conversion (W)
__global__ __launch_bounds__(256) void split_kernel(const float* __restrict__ s,
                                                    bf16* __restrict__ hi,
                                                    bf16* __restrict__ lo, int n4) {
    const int i = blockIdx.x * 256 + threadIdx.x;
    if (i >= n4) return;
    float4 v = reinterpret_cast<const float4*>(s)[i];
    bf16 h0 = __float2bfloat16(v.x), h1 = __float2bfloat16(v.y);
    bf16 h2 = __float2bfloat16(v.z), h3 = __float2bfloat16(v.w);
    uint2 uh, ul;
    uh.x = packbf(__bfloat162float(h0), __bfloat162float(h1));
    uh.y = packbf(__bfloat162float(h2), __bfloat162float(h3));
    ul.x = packbf(v.x - __bfloat162float(h0), v.y - __bfloat162float(h1));
    ul.y = packbf(v.z - __bfloat162float(h2), v.w - __bfloat162float(h3));
    reinterpret_cast<uint2*>(hi)[i] = uh;
    reinterpret_cast<uint2*>(lo)[i] = ul;
}

// mask -> additive float vector (0 / -inf)
__global__ __launch_bounds__(256) void mask_kernel(const int* __restrict__ x_mask) {
    const int i = blockIdx.x * 256 + threadIdx.x;
    if (i < BATCH * LSEQ)
        g_maskv[i] = x_mask[i] ? -INFINITY : 0.f;
}

// ---------------------------------------------------------------------------
extern "C" void kernel_launch(void* const* d_in, const int* in_sizes, int n_in,
                              void* d_out, int out_size) {
    const float* x      = (const float*)d_in[0];   // [8, 2048, 1024]
    const int*   x_mask = (const int*)d_in[1];     // [8, 2048]
    const float* W      = (const float*)d_in[2];   // [1024, 1024]
    const float* bias   = (const float*)d_in[3];   // [1024]
    float* out = (float*)d_out;                    // [8, 2048, 1024]

    cudaFuncSetAttribute(proj_gemm,   cudaFuncAttributeMaxDynamicSharedMemorySize, SMEM_BYTES);
    cudaFuncSetAttribute(scores_gemm, cudaFuncAttributeMaxDynamicSharedMemorySize, SMEM_SC);
    cudaFuncSetAttribute(av_gemm,     cudaFuncAttributeMaxDynamicSharedMemorySize, SMEM_AV);

    bf16 *wh, *wl;
    cudaGetSymbolAddress((void**)&wh, g_wh);
    cudaGetSymbolAddress((void**)&wl, g_wl);

    const int nw4 = DDIM * DDIM / 4;

    split_kernel<<<(nw4 + 255) / 256, 256>>>(W, wh, wl, nw4);
    mask_kernel<<<(BATCH * LSEQ + 255) / 256, 256>>>(x_mask);
    prep_x_kernel<<<dim3(DDIM / 32, LSEQ / 32, BATCH), 256>>>(x);

    proj_gemm  <<<dim3(DDIM / 128, (BATCH * LSEQ) / 128), NTH, SMEM_BYTES>>>(bias);
    scores_gemm<<<dim3(72, BATCH), NTH, SMEM_SC>>>();
    softmax_kernel<<<BATCH * LSEQ, 256>>>();
    av_gemm    <<<dim3(DDIM / 128, LSEQ / 128, BATCH), NTH_AV, SMEM_AV>>>(out);
}

// round 16
// speedup vs baseline: 1.1357x; 1.1249x over previous
#include <cuda_runtime.h>
#include <cuda_bf16.h>
#include <cuda_fp16.h>
#include <stdint.h>
#include <math.h>

#define BATCH 8
#define LSEQ  2048
#define DDIM  1024

typedef __nv_bfloat16 bf16;

// ---------------------------------------------------------------------------
// Scratch (device globals: no allocation allowed)
// ---------------------------------------------------------------------------
__device__ float  g_scores[(size_t)BATCH * LSEQ * LSEQ];           // 134 MB
__device__ float  g_maskv [(size_t)BATCH * LSEQ];                  // additive mask
__device__ bf16   g_xh [(size_t)BATCH * LSEQ * DDIM];
__device__ bf16   g_xl [(size_t)BATCH * LSEQ * DDIM];
__device__ __half g_xth[(size_t)BATCH * DDIM * LSEQ];              // x^T fp16 hi
__device__ bf16   g_wh [(size_t)DDIM * DDIM];
__device__ bf16   g_wl [(size_t)DDIM * DDIM];
__device__ bf16   g_ph [(size_t)BATCH * LSEQ * DDIM];
__device__ bf16   g_pl [(size_t)BATCH * LSEQ * DDIM];
__device__ __half g_ah [(size_t)BATCH * LSEQ * LSEQ];              // alpha fp16

// ---------------------------------------------------------------------------
// PTX helpers (base sm_103 target — NO tcgen05)
// ---------------------------------------------------------------------------
__device__ __forceinline__ uint32_t smem_u32(const void* p) {
    uint32_t a;
    asm("{ .reg .u64 t; cvta.to.shared.u64 t, %1; cvt.u32.u64 %0, t; }" : "=r"(a) : "l"(p));
    return a;
}

__device__ __forceinline__ void cpa16(uint32_t d, const void* s) {
    asm volatile("cp.async.cg.shared.global [%0], [%1], 16;" :: "r"(d), "l"(s) : "memory");
}

#define CP_COMMIT() asm volatile("cp.async.commit_group;" ::: "memory")
#define CP_WAIT1()  asm volatile("cp.async.wait_group 1;" ::: "memory")

#define LDSM4(r, addr) \
    asm volatile("ldmatrix.sync.aligned.m8n8.x4.shared.b16 {%0,%1,%2,%3}, [%4];" \
        : "=r"((r)[0]), "=r"((r)[1]), "=r"((r)[2]), "=r"((r)[3]) : "r"(addr))

#define MMA(d, a, b0, b1) \
    asm volatile("mma.sync.aligned.m16n8k16.row.col.f32.bf16.bf16.f32 " \
        "{%0,%1,%2,%3}, {%4,%5,%6,%7}, {%8,%9}, {%0,%1,%2,%3};" \
        : "+f"((d)[0]), "+f"((d)[1]), "+f"((d)[2]), "+f"((d)[3]) \
        : "r"((a)[0]), "r"((a)[1]), "r"((a)[2]), "r"((a)[3]), "r"(b0), "r"(b1))

#define MMAH(d, a, b0, b1) \
    asm volatile("mma.sync.aligned.m16n8k16.row.col.f32.f16.f16.f32 " \
        "{%0,%1,%2,%3}, {%4,%5,%6,%7}, {%8,%9}, {%0,%1,%2,%3};" \
        : "+f"((d)[0]), "+f"((d)[1]), "+f"((d)[2]), "+f"((d)[3]) \
        : "r"((a)[0]), "r"((a)[1]), "r"((a)[2]), "r"((a)[3]), "r"(b0), "r"(b1))

// ---------------------------------------------------------------------------
// 3-pass bf16 GEMM core (proj/scores): C(128x128) = (Ah+Al)(Bh+Bl)^T
// Stage = K=64 (64KB): A panels +0,+16384; B panels +32768,+49152.
// Panel row = 128B [hi 32k | lo 32k], XOR swizzle. 3 stages (192KB).
// 512 threads, 16 warps (4x4), warp tile 32x32. Frags double-buffered.
// ---------------------------------------------------------------------------
#define NTH 512
#define STG    65536
#define SMEM_BYTES (3 * STG)

struct Frag {
    uint32_t aH[2][4], aL[2][4], bH[2][4], bL[2][4];
};

__device__ __forceinline__ void issue_stage(uint32_t sb, int s, int tid,
    const bf16* __restrict__ Ah, const bf16* __restrict__ Al, size_t lda,
    const bf16* __restrict__ Bh, const bf16* __restrict__ Bl, size_t ldb, int kc)
{
    const uint32_t base = sb + (uint32_t)(s % 3) * STG;
    #pragma unroll
    for (int panel = 0; panel < 2; panel++) {
        const int kcp = kc + panel * 32;
        const uint32_t pb = base + (uint32_t)panel * 16384;
        #pragma unroll
        for (int j = 0; j < 2; j++) {
            const int q   = tid + j * NTH;       // 0..1023
            const int row = q >> 3;
            const int c   = q & 7;               // 0-3 hi, 4-7 lo
            const uint32_t off = (uint32_t)(row * 128) + ((uint32_t)(c ^ (row & 7)) << 4);
            const bf16* sa = (c < 4) ? Ah + (size_t)row * lda + kcp + c * 8
                                     : Al + (size_t)row * lda + kcp + (c - 4) * 8;
            const bf16* sbp = (c < 4) ? Bh + (size_t)row * ldb + kcp + c * 8
                                      : Bl + (size_t)row * ldb + kcp + (c - 4) * 8;
            cpa16(pb + off, sa);
            cpa16(pb + 32768 + off, sbp);
        }
    }
    CP_COMMIT();
}

__device__ __forceinline__ void load_frags(uint32_t stage, int kk, int m0, int n0,
                                           int lane, Frag& f)
{
    const uint32_t base = stage + (uint32_t)(kk >> 1) * 16384;
    const int cb = (kk & 1) * 2;
    const int rA = lane & 15, cA = lane >> 4;
    const int rB = (lane & 7) + ((lane >> 4) << 3), cB = (lane >> 3) & 1;
    #pragma unroll
    for (int mt = 0; mt < 2; mt++) {
        const uint32_t rowb = base + (uint32_t)((m0 + mt * 16 + rA) * 128);
        LDSM4(f.aH[mt], rowb + ((uint32_t)((cb + cA)     ^ (rA & 7)) << 4));
        LDSM4(f.aL[mt], rowb + ((uint32_t)((cb + 4 + cA) ^ (rA & 7)) << 4));
    }
    #pragma unroll
    for (int nt2 = 0; nt2 < 2; nt2++) {
        const uint32_t rowb = base + 32768 + (uint32_t)((n0 + nt2 * 16 + rB) * 128);
        LDSM4(f.bH[nt2], rowb + ((uint32_t)((cb + cB)     ^ (rB & 7)) << 4));
        LDSM4(f.bL[nt2], rowb + ((uint32_t)((cb + 4 + cB) ^ (rB & 7)) << 4));
    }
}

__device__ __forceinline__ void do_mmas(const Frag& f, float acc[2][4][4]) {
    #pragma unroll
    for (int mt = 0; mt < 2; mt++)
        #pragma unroll
        for (int nt = 0; nt < 4; nt++) {
            const int g = nt >> 1, o = (nt & 1) * 2;
            MMA(acc[mt][nt], f.aH[mt], f.bH[g][o], f.bH[g][o + 1]);
        }
    #pragma unroll
    for (int mt = 0; mt < 2; mt++)
        #pragma unroll
        for (int nt = 0; nt < 4; nt++) {
            const int g = nt >> 1, o = (nt & 1) * 2;
            MMA(acc[mt][nt], f.aH[mt], f.bL[g][o], f.bL[g][o + 1]);
        }
    #pragma unroll
    for (int mt = 0; mt < 2; mt++)
        #pragma unroll
        for (int nt = 0; nt < 4; nt++) {
            const int g = nt >> 1, o = (nt & 1) * 2;
            MMA(acc[mt][nt], f.aL[mt], f.bH[g][o], f.bH[g][o + 1]);
        }
}

__device__ __forceinline__ void run_gemm(uint32_t sb, int tid,
    const bf16* __restrict__ Ah, const bf16* __restrict__ Al, size_t lda,
    const bf16* __restrict__ Bh, const bf16* __restrict__ Bl, size_t ldb, int nk,
    float acc[2][4][4])
{
    #pragma unroll
    for (int mt = 0; mt < 2; mt++)
        #pragma unroll
        for (int nt = 0; nt < 4; nt++)
            #pragma unroll
            for (int i = 0; i < 4; i++) acc[mt][nt][i] = 0.f;

    issue_stage(sb, 0, tid, Ah, Al, lda, Bh, Bl, ldb, 0);
    issue_stage(sb, 1, tid, Ah, Al, lda, Bh, Bl, ldb, 64);

    const int wid = tid >> 5, lane = tid & 31;
    const int m0 = (wid & 3) * 32, n0 = (wid >> 2) * 32;

    CP_WAIT1();
    __syncthreads();

    Frag fa, fb;
    load_frags(sb, 0, m0, n0, lane, fa);

    for (int kt = 0; kt < nk; kt++) {
        const uint32_t cur = sb + (uint32_t)(kt % 3) * STG;
        if (kt + 2 < nk)
            issue_stage(sb, kt + 2, tid, Ah, Al, lda, Bh, Bl, ldb, (kt + 2) * 64);
        else
            CP_COMMIT();

        load_frags(cur, 1, m0, n0, lane, fb);
        do_mmas(fa, acc);
        load_frags(cur, 2, m0, n0, lane, fa);
        do_mmas(fb, acc);
        load_frags(cur, 3, m0, n0, lane, fb);
        do_mmas(fa, acc);

        CP_WAIT1();
        __syncthreads();

        const int pkt = (kt + 1 < nk) ? kt + 1 : kt;
        load_frags(sb + (uint32_t)(pkt % 3) * STG, 0, m0, n0, lane, fa);
        do_mmas(fb, acc);
    }
}

// ---------------------------------------------------------------------------
// 1-pass fp16 GEMM core (av): C(128x128) = Ah @ Bh^T.
// 256 threads, warp 64x32, K=64 stages x3 (96KB) -> 2 CTAs/SM, frag dbl-buf.
// ---------------------------------------------------------------------------
#define NTH_AV 256
#define STG_AV 32768
#define SMEM_AV (3 * STG_AV)

struct FragAv {
    uint32_t aH[4][4], bH[2][4];
};

__device__ __forceinline__ void issue_stage_av(uint32_t sb, int s, int tid,
    const __half* __restrict__ Ah, size_t lda,
    const __half* __restrict__ Bh, size_t ldb, int kc)
{
    const uint32_t base = sb + (uint32_t)(s % 3) * STG_AV;
    #pragma unroll
    for (int j = 0; j < 4; j++) {
        const int q   = tid + j * NTH_AV;
        const int row = q >> 3;
        const int c   = q & 7;
        const uint32_t off = (uint32_t)(row * 128) + ((uint32_t)(c ^ (row & 7)) << 4);
        cpa16(base + off, Ah + (size_t)row * lda + kc + c * 8);
    }
    #pragma unroll
    for (int j = 0; j < 4; j++) {
        const int q   = tid + j * NTH_AV;
        const int row = q >> 3;
        const int c   = q & 7;
        const uint32_t off = 16384u + (uint32_t)(row * 128)
                           + ((uint32_t)(c ^ (row & 7)) << 4);
        cpa16(base + off, Bh + (size_t)row * ldb + kc + c * 8);
    }
    CP_COMMIT();
}

__device__ __forceinline__ void load_frags_av(uint32_t stage, int kk, int m0, int n0,
                                              int lane, FragAv& f)
{
    const int cb = kk * 2;
    const int rA = lane & 15, cA = lane >> 4;
    const int rB = (lane & 7) + ((lane >> 4) << 3), cB = (lane >> 3) & 1;
    #pragma unroll
    for (int mt = 0; mt < 4; mt++) {
        const uint32_t rowb = stage + (uint32_t)((m0 + mt * 16 + rA) * 128);
        LDSM4(f.aH[mt], rowb + ((uint32_t)((cb + cA) ^ (rA & 7)) << 4));
    }
    #pragma unroll
    for (int nt2 = 0; nt2 < 2; nt2++) {
        const uint32_t rowb = stage + 16384 + (uint32_t)((n0 + nt2 * 16 + rB) * 128);
        LDSM4(f.bH[nt2], rowb + ((uint32_t)((cb + cB) ^ (rB & 7)) << 4));
    }
}

__device__ __forceinline__ void do_mmas_av(const FragAv& f, float acc[4][4][4]) {
    #pragma unroll
    for (int mt = 0; mt < 4; mt++)
        #pragma unroll
        for (int nt = 0; nt < 4; nt++) {
            const int g = nt >> 1, o = (nt & 1) * 2;
            MMAH(acc[mt][nt], f.aH[mt], f.bH[g][o], f.bH[g][o + 1]);
        }
}

__device__ __forceinline__ void run_gemm_av(uint32_t sb, int tid,
    const __half* __restrict__ Ah, size_t lda,
    const __half* __restrict__ Bh, size_t ldb, int nk,
    float acc[4][4][4])
{
    #pragma unroll
    for (int mt = 0; mt < 4; mt++)
        #pragma unroll
        for (int nt = 0; nt < 4; nt++)
            #pragma unroll
            for (int i = 0; i < 4; i++) acc[mt][nt][i] = 0.f;

    issue_stage_av(sb, 0, tid, Ah, lda, Bh, ldb, 0);
    issue_stage_av(sb, 1, tid, Ah, lda, Bh, ldb, 64);

    const int wid = tid >> 5, lane = tid & 31;
    const int m0 = (wid & 1) * 64, n0 = (wid >> 1) * 32;

    CP_WAIT1();
    __syncthreads();

    FragAv fa, fb;
    load_frags_av(sb, 0, m0, n0, lane, fa);

    for (int kt = 0; kt < nk; kt++) {
        const uint32_t cur = sb + (uint32_t)(kt % 3) * STG_AV;
        if (kt + 2 < nk)
            issue_stage_av(sb, kt + 2, tid, Ah, lda, Bh, ldb, (kt + 2) * 64);
        else
            CP_COMMIT();

        load_frags_av(cur, 1, m0, n0, lane, fb);
        do_mmas_av(fa, acc);
        load_frags_av(cur, 2, m0, n0, lane, fa);
        do_mmas_av(fb, acc);
        load_frags_av(cur, 3, m0, n0, lane, fb);
        do_mmas_av(fa, acc);

        CP_WAIT1();
        __syncthreads();

        const int pkt = (kt + 1 < nk) ? kt + 1 : kt;
        load_frags_av(sb + (uint32_t)(pkt % 3) * STG_AV, 0, m0, n0, lane, fa);
        do_mmas_av(fb, acc);
    }
}

__device__ __forceinline__ uint32_t packbf(float a, float b) {
    __nv_bfloat162 t = __floats2bfloat162_rn(a, b);
    return *reinterpret_cast<uint32_t*>(&t);
}
__device__ __forceinline__ uint32_t packh(float a, float b) {
    __half2 t = __floats2half2_rn(a, b);
    return *reinterpret_cast<uint32_t*>(&t);
}

// ---------------------------------------------------------------------------
// GEMM 1: proj = relu(x @ W^T + b) -> split bf16
// ---------------------------------------------------------------------------
__global__ __launch_bounds__(NTH, 1) void proj_gemm(const float* __restrict__ bias) {
    extern __shared__ char smem[];
    const uint32_t sb = smem_u32(smem);
    const int tid = threadIdx.x;
    const int mblk = blockIdx.y * 128, nblk = blockIdx.x * 128;

    float acc[2][4][4];
    run_gemm(sb, tid,
             g_xh + (size_t)mblk * DDIM, g_xl + (size_t)mblk * DDIM, DDIM,
             g_wh + (size_t)nblk * DDIM, g_wl + (size_t)nblk * DDIM, DDIM,
             DDIM / 64, acc);

    const int wid = tid >> 5, lane = tid & 31;
    const int m0 = (wid & 3) * 32, n0 = (wid >> 2) * 32;
    const int quad = lane >> 2, tq = lane & 3;

    #pragma unroll
    for (int mt = 0; mt < 2; mt++)
        #pragma unroll
        for (int nt = 0; nt < 4; nt++) {
            const int col = nblk + n0 + nt * 8 + tq * 2;
            const float b0 = bias[col], b1 = bias[col + 1];
            #pragma unroll
            for (int h = 0; h < 2; h++) {
                const int row = mblk + m0 + mt * 16 + quad + h * 8;
                float v0 = fmaxf(acc[mt][nt][h * 2 + 0] + b0, 0.f);
                float v1 = fmaxf(acc[mt][nt][h * 2 + 1] + b1, 0.f);
                bf16 h0 = __float2bfloat16(v0), h1 = __float2bfloat16(v1);
                float l0 = v0 - __bfloat162float(h0), l1 = v1 - __bfloat162float(h1);
                *reinterpret_cast<uint32_t*>(g_ph + (size_t)row * DDIM + col) =
                    packbf(__bfloat162float(h0), __bfloat162float(h1));
                *reinterpret_cast<uint32_t*>(g_pl + (size_t)row * DDIM + col) =
                    packbf(l0, l1);
            }
        }
}

// ---------------------------------------------------------------------------
// GEMM 2 (symmetric): off-diagonal pairs (ti<tj) first, diagonal tiles last
// (cheaper epilogue in the tail wave). Direct tile written straight from
// registers; smem staging only for the mirror tile. Raw scores; mask/diag in
// softmax.
// ---------------------------------------------------------------------------
__global__ __launch_bounds__(NTH, 1) void scores_gemm() {
    extern __shared__ char smem[];
    const uint32_t sb = smem_u32(smem);
    const int tid = threadIdx.x;
    const int b = blockIdx.y;

    int ti, tj;
    int p = blockIdx.x;
    if (p < 120) {                       // off-diagonal pairs ti < tj
        ti = 0;
        while (p >= 15 - ti) { p -= 15 - ti; ti++; }
        tj = ti + 1 + p;
    } else {                             // diagonal tiles, scheduled last
        ti = tj = p - 120;
    }
    const size_t pb = (size_t)b * LSEQ * DDIM;

    float acc[2][4][4];
    run_gemm(sb, tid,
             g_ph + pb + (size_t)ti * 128 * DDIM, g_pl + pb + (size_t)ti * 128 * DDIM, DDIM,
             g_ph + pb + (size_t)tj * 128 * DDIM, g_pl + pb + (size_t)tj * 128 * DDIM, DDIM,
             DDIM / 64, acc);

    const int wid = tid >> 5, lane = tid & 31;
    const int m0 = (wid & 3) * 32, n0 = (wid >> 2) * 32;
    const int quad = lane >> 2, tq = lane & 3;
    float* S = g_scores + (size_t)b * LSEQ * LSEQ;

    if (ti == tj) {
        // diagonal tile: direct write only, straight from registers
        #pragma unroll
        for (int mt = 0; mt < 2; mt++)
            #pragma unroll
            for (int nt = 0; nt < 4; nt++) {
                const int col = tj * 128 + n0 + nt * 8 + tq * 2;
                #pragma unroll
                for (int h = 0; h < 2; h++) {
                    const int row = ti * 128 + m0 + mt * 16 + quad + h * 8;
                    float2 o;
                    o.x = acc[mt][nt][h * 2 + 0];
                    o.y = acc[mt][nt][h * 2 + 1];
                    *reinterpret_cast<float2*>(S + (size_t)row * LSEQ + col) = o;
                }
            }
        return;
    }

    // off-diagonal: stage into smem for the mirror while writing direct tile
    __syncthreads();
    float (*sS)[129] = reinterpret_cast<float(*)[129]>(smem);

    #pragma unroll
    for (int mt = 0; mt < 2; mt++)
        #pragma unroll
        for (int nt = 0; nt < 4; nt++) {
            const int c = n0 + nt * 8 + tq * 2;
            #pragma unroll
            for (int h = 0; h < 2; h++) {
                const int r = m0 + mt * 16 + quad + h * 8;
                sS[r][c]     = acc[mt][nt][h * 2 + 0];
                sS[r][c + 1] = acc[mt][nt][h * 2 + 1];
            }
        }

    // direct tile from registers (overlaps the staging stores)
    #pragma unroll
    for (int mt = 0; mt < 2; mt++)
        #pragma unroll
        for (int nt = 0; nt < 4; nt++) {
            const int col = tj * 128 + n0 + nt * 8 + tq * 2;
            #pragma unroll
            for (int h = 0; h < 2; h++) {
                const int row = ti * 128 + m0 + mt * 16 + quad + h * 8;
                float2 o;
                o.x = acc[mt][nt][h * 2 + 0];
                o.y = acc[mt][nt][h * 2 + 1];
                *reinterpret_cast<float2*>(S + (size_t)row * LSEQ + col) = o;
            }
        }
    __syncthreads();

    // mirror tile: rows tj*128 + r, cols ti*128 + c, value sS[c][r]
    const int r  = tid & 127;
    const int c0 = (tid >> 7) * 32;
    float* Mrow = S + (size_t)(tj * 128 + r) * LSEQ + ti * 128;
    #pragma unroll
    for (int cc = 0; cc < 32; cc += 4) {
        const int c = c0 + cc;
        float4 v;
        v.x = sS[c][r];
        v.y = sS[c + 1][r];
        v.z = sS[c + 2][r];
        v.w = sS[c + 3][r];
        *reinterpret_cast<float4*>(Mrow + c) = v;
    }
}

// ---------------------------------------------------------------------------
// GEMM 3: out = alpha @ x   (fp16 1-pass, CTA 128x128, warp 64x32, 2 CTA/SM)
// ---------------------------------------------------------------------------
__global__ __launch_bounds__(NTH_AV, 2) void av_gemm(float* __restrict__ out) {
    extern __shared__ char smem[];
    const uint32_t sb = smem_u32(smem);
    const int tid = threadIdx.x;
    const int b = blockIdx.z;
    const int mblk = blockIdx.y * 128, nblk = blockIdx.x * 128;

    float acc[4][4][4];
    run_gemm_av(sb, tid,
                g_ah + ((size_t)b * LSEQ + mblk) * LSEQ, LSEQ,
                g_xth + ((size_t)b * DDIM + nblk) * LSEQ, LSEQ,
                LSEQ / 64, acc);

    const int wid = tid >> 5, lane = tid & 31;
    const int m0 = (wid & 1) * 64, n0 = (wid >> 1) * 32;
    const int quad = lane >> 2, tq = lane & 3;

    #pragma unroll
    for (int mt = 0; mt < 4; mt++)
        #pragma unroll
        for (int nt = 0; nt < 4; nt++) {
            const int col = nblk + n0 + nt * 8 + tq * 2;
            #pragma unroll
            for (int h = 0; h < 2; h++) {
                const int row = mblk + m0 + mt * 16 + quad + h * 8;
                float2 o;
                o.x = acc[mt][nt][h * 2 + 0];
                o.y = acc[mt][nt][h * 2 + 1];
                *reinterpret_cast<float2*>(out + ((size_t)b * LSEQ + row) * DDIM + col) = o;
            }
        }
}

// ---------------------------------------------------------------------------
// Softmax over keys (mask + diag applied here via g_maskv)
// ---------------------------------------------------------------------------
__global__ __launch_bounds__(256) void softmax_kernel() {
    const size_t row = blockIdx.x;
    const int b  = (int)(row >> 11);
    const int gi = (int)(row & (LSEQ - 1));
    const float* p  = g_scores + row * LSEQ;
    const float* mv = g_maskv + (size_t)b * LSEQ;
    const int t = threadIdx.x;

    float4 v0 = reinterpret_cast<const float4*>(p)[t * 2];
    float4 v1 = reinterpret_cast<const float4*>(p)[t * 2 + 1];
    float4 m0 = reinterpret_cast<const float4*>(mv)[t * 2];
    float4 m1 = reinterpret_cast<const float4*>(mv)[t * 2 + 1];

    float v[8];
    v[0] = v0.x + m0.x; v[1] = v0.y + m0.y; v[2] = v0.z + m0.z; v[3] = v0.w + m0.w;
    v[4] = v1.x + m1.x; v[5] = v1.y + m1.y; v[6] = v1.z + m1.z; v[7] = v1.w + m1.w;
    const int base = t * 8;
    if (gi >= base && gi < base + 8) {
        const float md[8] = {m0.x, m0.y, m0.z, m0.w, m1.x, m1.y, m1.z, m1.w};
        v[gi - base] = md[gi - base];
    }

    float m = v[0];
    #pragma unroll
    for (int i = 1; i < 8; i++) m = fmaxf(m, v[i]);

    __shared__ float red[8];
    #pragma unroll
    for (int off = 16; off > 0; off >>= 1)
        m = fmaxf(m, __shfl_xor_sync(0xffffffffu, m, off));
    if ((t & 31) == 0) red[t >> 5] = m;
    __syncthreads();
    if (t == 0) {
        float mm = red[0];
        #pragma unroll
        for (int w = 1; w < 8; w++) mm = fmaxf(mm, red[w]);
        red[0] = mm;
    }
    __syncthreads();
    m = red[0];
    __syncthreads();

    float e[8];
    #pragma unroll
    for (int i = 0; i < 8; i++) e[i] = __expf(v[i] - m);
    float s = e[0] + e[1] + e[2] + e[3] + e[4] + e[5] + e[6] + e[7];
    #pragma unroll
    for (int off = 16; off > 0; off >>= 1)
        s += __shfl_xor_sync(0xffffffffu, s, off);
    if ((t & 31) == 0) red[t >> 5] = s;
    __syncthreads();
    if (t == 0) {
        float ss = 0.f;
        #pragma unroll
        for (int w = 0; w < 8; w++) ss += red[w];
        red[0] = ss;
    }
    __syncthreads();
    const float inv = 1.0f / red[0];

    uint32_t hh[4];
    #pragma unroll
    for (int i = 0; i < 4; i++)
        hh[i] = packh(e[2 * i] * inv, e[2 * i + 1] * inv);
    *reinterpret_cast<uint4*>(g_ah + row * LSEQ + t * 8) = *reinterpret_cast<uint4*>(hh);
}

// ---------------------------------------------------------------------------
// Fused x prep: read x once -> xh/xl (row-major bf16) + xth (fp16 transposed)
// ---------------------------------------------------------------------------
__global__ __launch_bounds__(256) void prep_x_kernel(const float* __restrict__ x) {
    __shared__ float t[32][33];
    const int b = blockIdx.z, d0 = blockIdx.x * 32, l0 = blockIdx.y * 32;
    const int tx = threadIdx.x & 31, ty = threadIdx.x >> 5;
    const float* xb = x + (size_t)b * LSEQ * DDIM;
    bf16* xh = g_xh + (size_t)b * LSEQ * DDIM;
    bf16* xl = g_xl + (size_t)b * LSEQ * DDIM;

    #pragma unroll
    for (int j = 0; j < 4; j++) {
        const int l = l0 + ty + j * 8;
        const float v = xb[(size_t)l * DDIM + d0 + tx];
        t[ty + j * 8][tx] = v;
        bf16 h = __float2bfloat16(v);
        xh[(size_t)l * DDIM + d0 + tx] = h;
        xl[(size_t)l * DDIM + d0 + tx] = __float2bfloat16(v - __bfloat162float(h));
    }
    __syncthreads();
    __half* oh = g_xth + (size_t)b * DDIM * LSEQ;
    #pragma unroll
    for (int j = 0; j < 4; j++) {
        float v = t[tx][ty + j * 8];
        oh[(size_t)(d0 + ty + j * 8) * LSEQ + l0 + tx] = __float2half_rn(v);
    }
}

// fp32 -> split-bf16 conversion (W)
__global__ __launch_bounds__(256) void split_kernel(const float* __restrict__ s,
                                                    bf16* __restrict__ hi,
                                                    bf16* __restrict__ lo, int n4) {
    const int i = blockIdx.x * 256 + threadIdx.x;
    if (i >= n4) return;
    float4 v = reinterpret_cast<const float4*>(s)[i];
    bf16 h0 = __float2bfloat16(v.x), h1 = __float2bfloat16(v.y);
    bf16 h2 = __float2bfloat16(v.z), h3 = __float2bfloat16(v.w);
    uint2 uh, ul;
    uh.x = packbf(__bfloat162float(h0), __bfloat162float(h1));
    uh.y = packbf(__bfloat162float(h2), __bfloat162float(h3));
    ul.x = packbf(v.x - __bfloat162float(h0), v.y - __bfloat162float(h1));
    ul.y = packbf(v.z - __bfloat162float(h2), v.w - __bfloat162float(h3));
    reinterpret_cast<uint2*>(hi)[i] = uh;
    reinterpret_cast<uint2*>(lo)[i] = ul;
}

// mask -> additive float vector (0 / -inf)
__global__ __launch_bounds__(256) void mask_kernel(const int* __restrict__ x_mask) {
    const int i = blockIdx.x * 256 + threadIdx.x;
    if (i < BATCH * LSEQ)
        g_maskv[i] = x_mask[i] ? -INFINITY : 0.f;
}

// ---------------------------------------------------------------------------
extern "C" void kernel_launch(void* const* d_in, const int* in_sizes, int n_in,
                              void* d_out, int out_size) {
    const float* x      = (const float*)d_in[0];   // [8, 2048, 1024]
    const int*   x_mask = (const int*)d_in[1];     // [8, 2048]
    const float* W      = (const float*)d_in[2];   // [1024, 1024]
    const float* bias   = (const float*)d_in[3];   // [1024]
    float* out = (float*)d_out;                    // [8, 2048, 1024]

    cudaFuncSetAttribute(proj_gemm,   cudaFuncAttributeMaxDynamicSharedMemorySize, SMEM_BYTES);
    cudaFuncSetAttribute(scores_gemm, cudaFuncAttributeMaxDynamicSharedMemorySize, SMEM_BYTES);
    cudaFuncSetAttribute(av_gemm,     cudaFuncAttributeMaxDynamicSharedMemorySize, SMEM_AV);

    bf16 *wh, *wl;
    cudaGetSymbolAddress((void**)&wh, g_wh);
    cudaGetSymbolAddress((void**)&wl, g_wl);

    const int nw4 = DDIM * DDIM / 4;

    split_kernel<<<(nw4 + 255) / 256, 256>>>(W, wh, wl, nw4);
    mask_kernel<<<(BATCH * LSEQ + 255) / 256, 256>>>(x_mask);
    prep_x_kernel<<<dim3(DDIM / 32, LSEQ / 32, BATCH), 256>>>(x);

    proj_gemm  <<<dim3(DDIM / 128, (BATCH * LSEQ) / 128), NTH, SMEM_BYTES>>>(bias);
    scores_gemm<<<dim3(136, BATCH), NTH, SMEM_BYTES>>>();
    softmax_kernel<<<BATCH * LSEQ, 256>>>();
    av_gemm    <<<dim3(DDIM / 128, LSEQ / 128, BATCH), NTH_AV, SMEM_AV>>>(out);
}